// round 1
// baseline (speedup 1.0000x reference)
#include <cuda_runtime.h>
#include <cuda_bf16.h>

#define NN   20000
#define EE   160000
#define DD   512
#define MAXD 10
#define BN_EPS 1e-5f

#define PAD 128                      // bucket padding granularity (= BM)
#define NORD (NN + 11*PAD)           // padded node-order capacity

// ---------------- device scratch (no allocations allowed) ----------------
__device__ float g_h[NN * DD];       // neighbor sums
__device__ float g_pre[NN * DD];     // pre-BN linear output
__device__ int   g_deg[NN];
__device__ int   g_rowptr[NN + 1];
__device__ int   g_cursor[NN];
__device__ int   g_csr[EE];
__device__ int   g_bcnt[11];
__device__ int   g_bcur[11];
__device__ int   g_border[12];       // padded bucket offsets
__device__ int   g_norder[NORD];     // nodes grouped by degree bucket, -1 = pad
__device__ float g_sum[DD];
__device__ float g_sumsq[DD];
__device__ float g_scale[DD];
__device__ float g_shift[DD];

// ---------------- init ----------------
__global__ void k_zero() {
    int i = blockIdx.x * blockDim.x + threadIdx.x;
    if (i < NN)   { g_deg[i] = 0; g_cursor[i] = 0; }
    if (i < NORD) { g_norder[i] = -1; }
    if (i < DD)   { g_sum[i] = 0.f; g_sumsq[i] = 0.f; }
    if (i < 11)   { g_bcnt[i] = 0; g_bcur[i] = 0; }
}

// ---------------- degree histogram ----------------
__global__ void k_hist(const int* __restrict__ dst) {
    int e = blockIdx.x * blockDim.x + threadIdx.x;
    if (e < EE) atomicAdd(&g_deg[dst[e]], 1);
}

// ---------------- exclusive scan of degrees (single block) ----------------
__global__ void k_scan() {
    __shared__ int sh[1024];
    __shared__ int s_carry;
    int t = threadIdx.x;
    if (t == 0) s_carry = 0;
    __syncthreads();
    for (int base = 0; base < NN; base += 1024) {
        int carry = s_carry;
        int i = base + t;
        int v = (i < NN) ? g_deg[i] : 0;
        int x = v;
        for (int off = 1; off < 1024; off <<= 1) {
            sh[t] = x; __syncthreads();
            if (t >= off) x += sh[t - off];
            __syncthreads();
        }
        if (i < NN) g_rowptr[i] = carry + x - v;     // exclusive
        if (t == 1023) s_carry = carry + x;
        __syncthreads();
    }
    if (t == 0) g_rowptr[NN] = s_carry;
}

// ---------------- bucket counts ----------------
__global__ void k_bucket_count() {
    int n = blockIdx.x * blockDim.x + threadIdx.x;
    if (n < NN) {
        int b = min(g_deg[n], MAXD);
        atomicAdd(&g_bcnt[b], 1);
    }
}

// ---------------- padded bucket offsets (trivial scan) ----------------
__global__ void k_bscan() {
    if (threadIdx.x == 0 && blockIdx.x == 0) {
        int off = 0;
        for (int b = 0; b < 11; b++) {
            g_border[b] = off;
            int c = g_bcnt[b];
            off += (c + PAD - 1) & ~(PAD - 1);
        }
        g_border[11] = off;
    }
}

// ---------------- scatter nodes into buckets ----------------
__global__ void k_scatter() {
    int n = blockIdx.x * blockDim.x + threadIdx.x;
    if (n < NN) {
        int b = min(g_deg[n], MAXD);
        int idx = g_border[b] + atomicAdd(&g_bcur[b], 1);
        g_norder[idx] = n;
    }
}

// ---------------- fill CSR (dst -> list of src) ----------------
__global__ void k_fillcsr(const int* __restrict__ src, const int* __restrict__ dst) {
    int e = blockIdx.x * blockDim.x + threadIdx.x;
    if (e < EE) {
        int d = dst[e];
        int pos = atomicAdd(&g_cursor[d], 1);
        g_csr[g_rowptr[d] + pos] = src[e];
    }
}

// ---------------- neighbor sum: h[v] = sum feats[u], u->v ----------------
__global__ void k_aggh(const float* __restrict__ feats) {
    int n = blockIdx.x;
    int t = threadIdx.x;                       // 128 threads, float4 lanes
    const float4* f4 = reinterpret_cast<const float4*>(feats);
    float4 acc = make_float4(0.f, 0.f, 0.f, 0.f);
    int beg = g_rowptr[n], end = g_rowptr[n + 1];
    for (int j = beg; j < end; j++) {
        int s = g_csr[j];
        float4 v = f4[(size_t)s * 128 + t];
        acc.x += v.x; acc.y += v.y; acc.z += v.z; acc.w += v.w;
    }
    reinterpret_cast<float4*>(g_h)[(size_t)n * 128 + t] = acc;
}

// ---------------- grouped SGEMM: pre = h@Wl[b] + feats@Wr[b] + bl[b] ----------------
// BM=128, BN=128, BK=8, 256 threads, 8x8 per thread
__global__ void __launch_bounds__(256)
k_gemm(const float* __restrict__ feats, const float* __restrict__ Wl,
       const float* __restrict__ Wr, const float* __restrict__ bl) {
    int row0 = blockIdx.y * 128;
    if (row0 >= g_border[11]) return;
    int b = 0;
    while (b < 10 && row0 >= g_border[b + 1]) b++;

    const float* WlB = Wl + (size_t)b * DD * DD;
    const float* WrB = Wr + (size_t)b * DD * DD;

    __shared__ float As[8][128];
    __shared__ float Bs[8][128];
    __shared__ int   nodes[128];

    int tid = threadIdx.x;
    if (tid < 128) nodes[tid] = g_norder[row0 + tid];
    __syncthreads();

    float acc[8][8];
#pragma unroll
    for (int i = 0; i < 8; i++)
#pragma unroll
        for (int j = 0; j < 8; j++) acc[i][j] = 0.f;

    int ty = tid / 16, tx = tid % 16;
    int am = tid >> 1, ak = (tid & 1) * 4;     // A: 2 threads per node row
    int bk = tid >> 5, bn = (tid & 31) * 4;    // B: 8k x 128n

    int colbase = blockIdx.x * 128;
    int myA = nodes[am];

#pragma unroll 1
    for (int half = 0; half < 2; half++) {
        const float* Asrc = half ? feats : g_h;
        const float* Bsrc = half ? WrB : WlB;
#pragma unroll 1
        for (int k0 = 0; k0 < DD; k0 += 8) {
            float4 av = make_float4(0.f, 0.f, 0.f, 0.f);
            if (myA >= 0)
                av = *reinterpret_cast<const float4*>(&Asrc[(size_t)myA * DD + k0 + ak]);
            As[ak + 0][am] = av.x; As[ak + 1][am] = av.y;
            As[ak + 2][am] = av.z; As[ak + 3][am] = av.w;
            float4 bv = *reinterpret_cast<const float4*>(
                &Bsrc[(size_t)(k0 + bk) * DD + colbase + bn]);
            *reinterpret_cast<float4*>(&Bs[bk][bn]) = bv;
            __syncthreads();
#pragma unroll
            for (int k = 0; k < 8; k++) {
                float a[8], q[8];
#pragma unroll
                for (int i = 0; i < 8; i++) a[i] = As[k][ty * 8 + i];
#pragma unroll
                for (int j = 0; j < 8; j++) q[j] = Bs[k][tx * 8 + j];
#pragma unroll
                for (int i = 0; i < 8; i++)
#pragma unroll
                    for (int j = 0; j < 8; j++) acc[i][j] += a[i] * q[j];
            }
            __syncthreads();
        }
    }

    // epilogue: + bl[b], scatter to g_pre
    int cb = colbase + tx * 8;
    float blv[8];
#pragma unroll
    for (int j = 0; j < 8; j++) blv[j] = bl[(size_t)b * DD + cb + j];
#pragma unroll
    for (int i = 0; i < 8; i++) {
        int node = nodes[ty * 8 + i];
        if (node < 0) continue;
        float* dst = &g_pre[(size_t)node * DD + cb];
        float4 v0 = make_float4(acc[i][0] + blv[0], acc[i][1] + blv[1],
                                acc[i][2] + blv[2], acc[i][3] + blv[3]);
        float4 v1 = make_float4(acc[i][4] + blv[4], acc[i][5] + blv[5],
                                acc[i][6] + blv[6], acc[i][7] + blv[7]);
        *reinterpret_cast<float4*>(dst)     = v0;
        *reinterpret_cast<float4*>(dst + 4) = v1;
    }
}

// ---------------- BN statistics: per-column sum & sumsq ----------------
__global__ void k_bnstats() {
    int r0 = blockIdx.x * 128;
    int r1 = min(r0 + 128, NN);
    int t = threadIdx.x;                      // 256 threads -> 2 cols each
    float s0 = 0.f, q0 = 0.f, s1 = 0.f, q1 = 0.f;
    for (int r = r0; r < r1; r++) {
        float v0 = g_pre[(size_t)r * DD + t];
        float v1 = g_pre[(size_t)r * DD + t + 256];
        s0 += v0; q0 += v0 * v0;
        s1 += v1; q1 += v1 * v1;
    }
    atomicAdd(&g_sum[t], s0);       atomicAdd(&g_sumsq[t], q0);
    atomicAdd(&g_sum[t + 256], s1); atomicAdd(&g_sumsq[t + 256], q1);
}

__global__ void k_bnfinal(const float* __restrict__ gamma, const float* __restrict__ beta) {
    int c = threadIdx.x;
    float mean = g_sum[c] / (float)NN;
    float var  = g_sumsq[c] / (float)NN - mean * mean;
    float sc = gamma[c] * rsqrtf(var + BN_EPS);
    g_scale[c] = sc;
    g_shift[c] = beta[c] - mean * sc;
}

// ---------------- max aggregation with self loop (BN applied on read) ----------------
__global__ void k_maxagg(float* __restrict__ out) {
    int n = blockIdx.x;
    int t = threadIdx.x;                       // 128 threads, float4 lanes
    const float4* p4 = reinterpret_cast<const float4*>(g_pre);
    float4 sc = reinterpret_cast<const float4*>(g_scale)[t];
    float4 sh = reinterpret_cast<const float4*>(g_shift)[t];
    float4 v = p4[(size_t)n * 128 + t];
    float4 m = make_float4(v.x * sc.x + sh.x, v.y * sc.y + sh.y,
                           v.z * sc.z + sh.z, v.w * sc.w + sh.w);
    int beg = g_rowptr[n], end = g_rowptr[n + 1];
    for (int j = beg; j < end; j++) {
        int u = g_csr[j];
        float4 w = p4[(size_t)u * 128 + t];
        m.x = fmaxf(m.x, w.x * sc.x + sh.x);
        m.y = fmaxf(m.y, w.y * sc.y + sh.y);
        m.z = fmaxf(m.z, w.z * sc.z + sh.z);
        m.w = fmaxf(m.w, w.w * sc.w + sh.w);
    }
    reinterpret_cast<float4*>(out)[(size_t)n * 128 + t] = m;
}

// ---------------- launch ----------------
extern "C" void kernel_launch(void* const* d_in, const int* in_sizes, int n_in,
                              void* d_out, int out_size) {
    const float* feats = (const float*)d_in[0];
    const int*   src   = (const int*)  d_in[1];
    const int*   dst   = (const int*)  d_in[2];
    const float* Wl    = (const float*)d_in[3];
    const float* Wr    = (const float*)d_in[4];
    const float* bl    = (const float*)d_in[5];
    const float* gamma = (const float*)d_in[6];
    const float* beta  = (const float*)d_in[7];
    float* out = (float*)d_out;

    k_zero<<<(NORD + 255) / 256, 256>>>();
    k_hist<<<(EE + 255) / 256, 256>>>(dst);
    k_scan<<<1, 1024>>>();
    k_bucket_count<<<(NN + 255) / 256, 256>>>();
    k_bscan<<<1, 32>>>();
    k_scatter<<<(NN + 255) / 256, 256>>>();
    k_fillcsr<<<(EE + 255) / 256, 256>>>(src, dst);
    k_aggh<<<NN, 128>>>(feats);
    k_gemm<<<dim3(4, 168), 256>>>(feats, Wl, Wr, bl);
    k_bnstats<<<(NN + 127) / 128, 256>>>();
    k_bnfinal<<<1, 512>>>(gamma, beta);
    k_maxagg<<<NN, 128>>>(out);
}

// round 8
// speedup vs baseline: 1.4375x; 1.4375x over previous
#include <cuda_runtime.h>
#include <cuda_bf16.h>
#include <cstdint>

#define NN   20000
#define EE   160000
#define DD   512
#define MAXD 10
#define BN_EPS 1e-5f

#define PAD 128
#define NORD (NN + 11*PAD)           // 21408

// ---------------- device scratch ----------------
__device__ float g_h[NN * DD];
__device__ float g_pre[NN * DD];
__device__ int   g_deg[NN];
__device__ int   g_rowptr[NN + 1];
__device__ int   g_cursor[NN];
__device__ int   g_csr[EE];
__device__ int   g_bcnt[11];
__device__ int   g_bcur[11];
__device__ int   g_border[12];
__device__ int   g_norder[NORD];
__device__ float g_sum[DD];
__device__ float g_sumsq[DD];
__device__ float g_scale[DD];
__device__ float g_shift[DD];
// packed bf16 operands (hi/lo split)
__device__ __nv_bfloat16 g_Ah[(size_t)NORD * 1024];
__device__ __nv_bfloat16 g_Al[(size_t)NORD * 1024];
__device__ __nv_bfloat16 g_Whi[(size_t)11 * 512 * 1024];   // [b][n][k] k-major
__device__ __nv_bfloat16 g_Wlo[(size_t)11 * 512 * 1024];

// ---------------- PTX helpers (Ampere-era, compute_103-safe) ----------------
__device__ __forceinline__ uint32_t smem_u32(const void* p) {
    uint32_t a;
    asm("{ .reg .u64 t; cvta.to.shared.u64 t, %1; cvt.u32.u64 %0, t; }" : "=r"(a) : "l"(p));
    return a;
}
__device__ __forceinline__ void cp_async16(uint32_t sdst, const void* gsrc) {
    asm volatile("cp.async.cg.shared.global [%0], [%1], 16;" :: "r"(sdst), "l"(gsrc));
}
#define CP_COMMIT() asm volatile("cp.async.commit_group;" ::: "memory")
#define CP_WAIT1()  asm volatile("cp.async.wait_group 1;" ::: "memory")
#define CP_WAIT0()  asm volatile("cp.async.wait_group 0;" ::: "memory")

__device__ __forceinline__ void ldsm4(uint32_t* r, uint32_t addr) {
    asm volatile("ldmatrix.sync.aligned.m8n8.x4.shared.b16 {%0,%1,%2,%3}, [%4];"
                 : "=r"(r[0]), "=r"(r[1]), "=r"(r[2]), "=r"(r[3]) : "r"(addr));
}
__device__ __forceinline__ void mma16816(float* c, const uint32_t* a, const uint32_t* b) {
    asm volatile(
        "mma.sync.aligned.m16n8k16.row.col.f32.bf16.bf16.f32 "
        "{%0,%1,%2,%3}, {%4,%5,%6,%7}, {%8,%9}, {%0,%1,%2,%3};"
        : "+f"(c[0]), "+f"(c[1]), "+f"(c[2]), "+f"(c[3])
        : "r"(a[0]), "r"(a[1]), "r"(a[2]), "r"(a[3]), "r"(b[0]), "r"(b[1]));
}

// ---------------- plumbing kernels ----------------
__global__ void k_zero() {
    int i = blockIdx.x * blockDim.x + threadIdx.x;
    if (i < NN)   { g_deg[i] = 0; g_cursor[i] = 0; }
    if (i < NORD) { g_norder[i] = -1; }
    if (i < DD)   { g_sum[i] = 0.f; g_sumsq[i] = 0.f; }
    if (i < 11)   { g_bcnt[i] = 0; g_bcur[i] = 0; }
}

__global__ void k_hist(const int* __restrict__ dst) {
    int e = blockIdx.x * blockDim.x + threadIdx.x;
    if (e < EE) atomicAdd(&g_deg[dst[e]], 1);
}

__global__ void k_scan() {
    __shared__ int sh[1024];
    __shared__ int s_carry;
    int t = threadIdx.x;
    if (t == 0) s_carry = 0;
    __syncthreads();
    for (int base = 0; base < NN; base += 1024) {
        int carry = s_carry;
        int i = base + t;
        int v = (i < NN) ? g_deg[i] : 0;
        int x = v;
        for (int off = 1; off < 1024; off <<= 1) {
            sh[t] = x; __syncthreads();
            if (t >= off) x += sh[t - off];
            __syncthreads();
        }
        if (i < NN) g_rowptr[i] = carry + x - v;
        if (t == 1023) s_carry = carry + x;
        __syncthreads();
    }
    if (t == 0) g_rowptr[NN] = s_carry;
}

__global__ void k_bucket_count() {
    int n = blockIdx.x * blockDim.x + threadIdx.x;
    if (n < NN) atomicAdd(&g_bcnt[min(g_deg[n], MAXD)], 1);
}

__global__ void k_bscan() {
    if (threadIdx.x == 0 && blockIdx.x == 0) {
        int off = 0;
        for (int b = 0; b < 11; b++) {
            g_border[b] = off;
            off += (g_bcnt[b] + PAD - 1) & ~(PAD - 1);
        }
        g_border[11] = off;
    }
}

__global__ void k_scatter() {
    int n = blockIdx.x * blockDim.x + threadIdx.x;
    if (n < NN) {
        int b = min(g_deg[n], MAXD);
        g_norder[g_border[b] + atomicAdd(&g_bcur[b], 1)] = n;
    }
}

__global__ void k_fillcsr(const int* __restrict__ src, const int* __restrict__ dst) {
    int e = blockIdx.x * blockDim.x + threadIdx.x;
    if (e < EE) {
        int d = dst[e];
        int pos = atomicAdd(&g_cursor[d], 1);
        g_csr[g_rowptr[d] + pos] = src[e];
    }
}

__global__ void k_aggh(const float* __restrict__ feats) {
    int n = blockIdx.x;
    int t = threadIdx.x;
    const float4* f4 = reinterpret_cast<const float4*>(feats);
    float4 acc = make_float4(0.f, 0.f, 0.f, 0.f);
    int beg = g_rowptr[n], end = g_rowptr[n + 1];
    for (int j = beg; j < end; j++) {
        float4 v = f4[(size_t)g_csr[j] * 128 + t];
        acc.x += v.x; acc.y += v.y; acc.z += v.z; acc.w += v.w;
    }
    reinterpret_cast<float4*>(g_h)[(size_t)n * 128 + t] = acc;
}

// ---------------- pack A: permuted rows, bf16 hi/lo, [row][h(512) | feats(512)] ----------------
__global__ void k_pack_a(const float* __restrict__ feats) {
    int row = blockIdx.x;
    if (row >= g_border[11]) return;
    int t = threadIdx.x;                 // 128 threads, 8 cols each
    int node = g_norder[row];
    int c0 = t * 8;
    __nv_bfloat16 hi[8], lo[8];
    if (node >= 0) {
        const float* src = (c0 < 512) ? (g_h + (size_t)node * 512 + c0)
                                      : (feats + (size_t)node * 512 + (c0 - 512));
        float4 v0 = *reinterpret_cast<const float4*>(src);
        float4 v1 = *reinterpret_cast<const float4*>(src + 4);
        float vv[8] = {v0.x, v0.y, v0.z, v0.w, v1.x, v1.y, v1.z, v1.w};
#pragma unroll
        for (int j = 0; j < 8; j++) {
            hi[j] = __float2bfloat16(vv[j]);
            lo[j] = __float2bfloat16(vv[j] - __bfloat162float(hi[j]));
        }
    } else {
#pragma unroll
        for (int j = 0; j < 8; j++) { hi[j] = __float2bfloat16(0.f); lo[j] = hi[j]; }
    }
    *reinterpret_cast<uint4*>(&g_Ah[(size_t)row * 1024 + c0]) = *reinterpret_cast<uint4*>(hi);
    *reinterpret_cast<uint4*>(&g_Al[(size_t)row * 1024 + c0]) = *reinterpret_cast<uint4*>(lo);
}

// ---------------- pack W: transpose to [b][n][k], k-major, bf16 hi/lo ----------------
__global__ void k_pack_w(const float* __restrict__ Wl, const float* __restrict__ Wr) {
    __shared__ float tile[32][33];
    int b = blockIdx.z >> 1, half = blockIdx.z & 1;
    int k0 = blockIdx.x * 32, n0 = blockIdx.y * 32;
    const float* W = (half ? Wr : Wl) + (size_t)b * 512 * 512;
    int tx = threadIdx.x, ty = threadIdx.y;      // (32, 8)
#pragma unroll
    for (int dy = 0; dy < 32; dy += 8)
        tile[ty + dy][tx] = W[(size_t)(k0 + ty + dy) * 512 + n0 + tx];
    __syncthreads();
#pragma unroll
    for (int dy = 0; dy < 32; dy += 8) {
        int n = n0 + ty + dy;
        float v = tile[tx][ty + dy];
        __nv_bfloat16 h = __float2bfloat16(v);
        __nv_bfloat16 l = __float2bfloat16(v - __bfloat162float(h));
        size_t o = ((size_t)b * 512 + n) * 1024 + (size_t)half * 512 + k0 + tx;
        g_Whi[o] = h;
        g_Wlo[o] = l;
    }
}

// ---------------- warp-MMA grouped GEMM ----------------
// CTA tile 128m x 128n, warp tile 32m x 64n, K-chunk 32, 96 chunks (3 bf16 passes x 1024K)
#define KCH 32
#define NCHUNK 96
#define APITCH 80                     // bytes per smem row (32 bf16 + 16B pad)
#define HALF_STAGE (128 * APITCH)     // 10240
#define STAGE (2 * HALF_STAGE)        // 20480

__device__ __forceinline__ void issue_chunk(uint32_t sbase, int c, int row0,
                                            int colbase, int b, int tid) {
    int pass = c >> 5, kc = (c & 31) * KCH;
    const __nv_bfloat16* Asrc = (pass < 2) ? g_Ah : g_Al;
    const __nv_bfloat16* Bsrc = (pass == 1) ? g_Wlo : g_Whi;
#pragma unroll
    for (int t = tid; t < 512; t += 256) {
        int row = t >> 2, seg = t & 3;
        cp_async16(sbase + row * APITCH + seg * 16,
                   Asrc + (size_t)(row0 + row) * 1024 + kc + seg * 8);
    }
#pragma unroll
    for (int t = tid; t < 512; t += 256) {
        int row = t >> 2, seg = t & 3;
        cp_async16(sbase + HALF_STAGE + row * APITCH + seg * 16,
                   Bsrc + ((size_t)b * 512 + colbase + row) * 1024 + kc + seg * 8);
    }
}

__global__ void __launch_bounds__(256, 1)
k_gemm_hmma(const float* __restrict__ bl) {
    int row0 = blockIdx.y * 128;
    if (row0 >= g_border[11]) return;
    int colbase = blockIdx.x * 128;
    int b = 0;
    while (b < 10 && row0 >= g_border[b + 1]) b++;

    __shared__ __align__(128) char sbuf[2][STAGE];
    __shared__ int nodes[128];

    int tid = threadIdx.x, w = tid >> 5, lane = tid & 31;
    if (tid < 128) nodes[tid] = g_norder[row0 + tid];

    uint32_t s0 = smem_u32(sbuf[0]);
    uint32_t s1 = smem_u32(sbuf[1]);

    float c[2][8][4];
#pragma unroll
    for (int i = 0; i < 2; i++)
#pragma unroll
        for (int j = 0; j < 8; j++)
#pragma unroll
            for (int q = 0; q < 4; q++) c[i][j][q] = 0.f;

    int mw = (w & 3) * 32, nw = (w >> 2) * 64;

    issue_chunk(s0, 0, row0, colbase, b, tid);
    CP_COMMIT();

#pragma unroll 1
    for (int i = 0; i < NCHUNK; i++) {
        if (i + 1 < NCHUNK)
            issue_chunk((i + 1) & 1 ? s1 : s0, i + 1, row0, colbase, b, tid);
        CP_COMMIT();
        CP_WAIT1();
        __syncthreads();

        uint32_t sb = (i & 1) ? s1 : s0;
#pragma unroll
        for (int ks = 0; ks < 2; ks++) {
            int k0 = ks * 16;
            uint32_t a[2][4];
#pragma unroll
            for (int am = 0; am < 2; am++) {
                int row = mw + am * 16 + (lane & 15);
                int col = k0 + (lane >> 4) * 8;
                ldsm4(a[am], sb + row * APITCH + col * 2);
            }
            uint32_t bf[4][4];
#pragma unroll
            for (int bp = 0; bp < 4; bp++) {
                int row = nw + bp * 16 + (lane & 7) + (lane >> 4) * 8;
                int col = k0 + ((lane >> 3) & 1) * 8;
                ldsm4(bf[bp], sb + HALF_STAGE + row * APITCH + col * 2);
            }
#pragma unroll
            for (int am = 0; am < 2; am++)
#pragma unroll
                for (int bp = 0; bp < 4; bp++) {
                    mma16816(c[am][bp * 2 + 0], a[am], &bf[bp][0]);
                    mma16816(c[am][bp * 2 + 1], a[am], &bf[bp][2]);
                }
        }
        __syncthreads();
    }

    // epilogue: + bias, scatter rows to g_pre[node]
#pragma unroll
    for (int am = 0; am < 2; am++) {
        int mloc = mw + am * 16 + (lane >> 2);
#pragma unroll
        for (int half = 0; half < 2; half++) {
            int node = nodes[mloc + half * 8];
            if (node < 0) continue;
#pragma unroll
            for (int bn = 0; bn < 8; bn++) {
                int col = colbase + nw + bn * 8 + (lane & 3) * 2;
                float bb0 = bl[(size_t)b * 512 + col];
                float bb1 = bl[(size_t)b * 512 + col + 1];
                float2 v = make_float2(c[am][bn][half * 2 + 0] + bb0,
                                       c[am][bn][half * 2 + 1] + bb1);
                *reinterpret_cast<float2*>(&g_pre[(size_t)node * 512 + col]) = v;
            }
        }
    }
}

// ---------------- BN ----------------
__global__ void k_bnstats() {
    int r0 = blockIdx.x * 128;
    int r1 = min(r0 + 128, NN);
    int t = threadIdx.x;
    float s0 = 0.f, q0 = 0.f, s1 = 0.f, q1 = 0.f;
    for (int r = r0; r < r1; r++) {
        float v0 = g_pre[(size_t)r * DD + t];
        float v1 = g_pre[(size_t)r * DD + t + 256];
        s0 += v0; q0 += v0 * v0;
        s1 += v1; q1 += v1 * v1;
    }
    atomicAdd(&g_sum[t], s0);       atomicAdd(&g_sumsq[t], q0);
    atomicAdd(&g_sum[t + 256], s1); atomicAdd(&g_sumsq[t + 256], q1);
}

__global__ void k_bnfinal(const float* __restrict__ gamma, const float* __restrict__ beta) {
    int c = threadIdx.x;
    float mean = g_sum[c] / (float)NN;
    float var  = g_sumsq[c] / (float)NN - mean * mean;
    float sc = gamma[c] * rsqrtf(var + BN_EPS);
    g_scale[c] = sc;
    g_shift[c] = beta[c] - mean * sc;
}

__global__ void k_maxagg(float* __restrict__ out) {
    int n = blockIdx.x;
    int t = threadIdx.x;
    const float4* p4 = reinterpret_cast<const float4*>(g_pre);
    float4 sc = reinterpret_cast<const float4*>(g_scale)[t];
    float4 sh = reinterpret_cast<const float4*>(g_shift)[t];
    float4 v = p4[(size_t)n * 128 + t];
    float4 m = make_float4(v.x * sc.x + sh.x, v.y * sc.y + sh.y,
                           v.z * sc.z + sh.z, v.w * sc.w + sh.w);
    int beg = g_rowptr[n], end = g_rowptr[n + 1];
    for (int j = beg; j < end; j++) {
        float4 w = p4[(size_t)g_csr[j] * 128 + t];
        m.x = fmaxf(m.x, w.x * sc.x + sh.x);
        m.y = fmaxf(m.y, w.y * sc.y + sh.y);
        m.z = fmaxf(m.z, w.z * sc.z + sh.z);
        m.w = fmaxf(m.w, w.w * sc.w + sh.w);
    }
    reinterpret_cast<float4*>(out)[(size_t)n * 128 + t] = m;
}

// ---------------- launch ----------------
extern "C" void kernel_launch(void* const* d_in, const int* in_sizes, int n_in,
                              void* d_out, int out_size) {
    const float* feats = (const float*)d_in[0];
    const int*   src   = (const int*)  d_in[1];
    const int*   dst   = (const int*)  d_in[2];
    const float* Wl    = (const float*)d_in[3];
    const float* Wr    = (const float*)d_in[4];
    const float* bl    = (const float*)d_in[5];
    const float* gamma = (const float*)d_in[6];
    const float* beta  = (const float*)d_in[7];
    float* out = (float*)d_out;

    k_zero<<<(NORD + 255) / 256, 256>>>();
    k_hist<<<(EE + 255) / 256, 256>>>(dst);
    k_scan<<<1, 1024>>>();
    k_bucket_count<<<(NN + 255) / 256, 256>>>();
    k_bscan<<<1, 32>>>();
    k_scatter<<<(NN + 255) / 256, 256>>>();
    k_fillcsr<<<(EE + 255) / 256, 256>>>(src, dst);
    k_aggh<<<NN, 128>>>(feats);
    k_pack_w<<<dim3(16, 16, 22), dim3(32, 8)>>>(Wl, Wr);
    k_pack_a<<<NORD, 128>>>(feats);
    k_gemm_hmma<<<dim3(4, 168), 256>>>(bl);
    k_bnstats<<<(NN + 127) / 128, 256>>>();
    k_bnfinal<<<1, 512>>>(gamma, beta);
    k_maxagg<<<NN, 128>>>(out);
}

// round 10
// speedup vs baseline: 1.8404x; 1.2803x over previous
#include <cuda_runtime.h>
#include <cuda_bf16.h>
#include <cstdint>

#define NN   20000
#define EE   160000
#define DD   512
#define MAXD 10
#define BN_EPS 1e-5f

#define PAD 128
#define NORD (NN + 11*PAD)           // 21408

// ---------------- device scratch ----------------
__device__ float g_pre[NN * DD];
__device__ int   g_deg[NN];
__device__ int   g_rowptr[NN + 1];
__device__ int   g_cursor[NN];
__device__ int   g_csr[EE];
__device__ int   g_bcur[11];
__device__ int   g_border[12];
__device__ int   g_norder[NORD];
__device__ float g_sum[DD];
__device__ float g_sumsq[DD];
// packed bf16 operands (hi/lo split), rows permuted by bucket: [row][h(512)|feats(512)]
__device__ __nv_bfloat16 g_Ah[(size_t)NORD * 1024];
__device__ __nv_bfloat16 g_Al[(size_t)NORD * 1024];
__device__ __nv_bfloat16 g_Whi[(size_t)11 * 512 * 1024];   // [b][n][k] k-major
__device__ __nv_bfloat16 g_Wlo[(size_t)11 * 512 * 1024];

// ---------------- PTX helpers (compute_103-safe) ----------------
__device__ __forceinline__ uint32_t smem_u32(const void* p) {
    uint32_t a;
    asm("{ .reg .u64 t; cvta.to.shared.u64 t, %1; cvt.u32.u64 %0, t; }" : "=r"(a) : "l"(p));
    return a;
}
__device__ __forceinline__ void cp_async16(uint32_t sdst, const void* gsrc) {
    asm volatile("cp.async.cg.shared.global [%0], [%1], 16;" :: "r"(sdst), "l"(gsrc));
}
#define CP_COMMIT() asm volatile("cp.async.commit_group;" ::: "memory")
#define CP_WAIT1()  asm volatile("cp.async.wait_group 1;" ::: "memory")

__device__ __forceinline__ void ldsm4(uint32_t* r, uint32_t addr) {
    asm volatile("ldmatrix.sync.aligned.m8n8.x4.shared.b16 {%0,%1,%2,%3}, [%4];"
                 : "=r"(r[0]), "=r"(r[1]), "=r"(r[2]), "=r"(r[3]) : "r"(addr));
}
__device__ __forceinline__ void mma16816(float* c, const uint32_t* a, const uint32_t* b) {
    asm volatile(
        "mma.sync.aligned.m16n8k16.row.col.f32.bf16.bf16.f32 "
        "{%0,%1,%2,%3}, {%4,%5,%6,%7}, {%8,%9}, {%0,%1,%2,%3};"
        : "+f"(c[0]), "+f"(c[1]), "+f"(c[2]), "+f"(c[3])
        : "r"(a[0]), "r"(a[1]), "r"(a[2]), "r"(a[3]), "r"(b[0]), "r"(b[1]));
}

// 64B-pitch smem swizzle: 16B segment s of row r goes to segment s ^ ((r>>1)&3).
// (r&1 picks the 64B half of a 128B line; the XOR makes all 8 ldsm rows distinct mod 128B.)
__device__ __forceinline__ uint32_t swz(int row, int seg) {
    return (uint32_t)(row * 64 + ((seg ^ ((row >> 1) & 3)) << 4));
}

// ---------------- plumbing ----------------
__global__ void k_zero() {
    int i = blockIdx.x * blockDim.x + threadIdx.x;
    if (i < NN)   { g_deg[i] = 0; g_cursor[i] = 0; }
    if (i < NORD) { g_norder[i] = -1; }
    if (i < DD)   { g_sum[i] = 0.f; g_sumsq[i] = 0.f; }
    if (i < 11)   { g_bcur[i] = 0; }
}

__global__ void k_hist(const int* __restrict__ dst) {
    int e = blockIdx.x * blockDim.x + threadIdx.x;
    if (e < EE) atomicAdd(&g_deg[dst[e]], 1);
}

// single block: exclusive scan of deg -> rowptr, bucket counts -> padded borders
__global__ void k_scan() {
    __shared__ int warp_sums[32];
    __shared__ int s_bcnt[11];
    __shared__ int s_carry;
    int t = threadIdx.x, lane = t & 31, w = t >> 5;
    if (t < 11) s_bcnt[t] = 0;
    if (t == 0) s_carry = 0;
    __syncthreads();
    for (int base = 0; base < NN; base += 1024) {
        int i = base + t;
        int v = (i < NN) ? g_deg[i] : 0;
        if (i < NN) atomicAdd(&s_bcnt[min(v, MAXD)], 1);
        int x = v;
#pragma unroll
        for (int o = 1; o < 32; o <<= 1) {
            int y = __shfl_up_sync(~0u, x, o);
            if (lane >= o) x += y;
        }
        if (lane == 31) warp_sums[w] = x;
        __syncthreads();
        if (w == 0) {
            int s = warp_sums[lane];
#pragma unroll
            for (int o = 1; o < 32; o <<= 1) {
                int y = __shfl_up_sync(~0u, s, o);
                if (lane >= o) s += y;
            }
            warp_sums[lane] = s;
        }
        __syncthreads();
        int prefix = s_carry + (w ? warp_sums[w - 1] : 0);
        if (i < NN) g_rowptr[i] = prefix + x - v;
        __syncthreads();
        if (t == 0) s_carry += warp_sums[31];
        __syncthreads();
    }
    if (t == 0) {
        g_rowptr[NN] = s_carry;
        int off = 0;
        for (int b = 0; b < 11; b++) {
            g_border[b] = off;
            off += (s_bcnt[b] + PAD - 1) & ~(PAD - 1);
        }
        g_border[11] = off;
    }
}

// scatter nodes into buckets + fill CSR, one kernel
__global__ void k_scatter_fill(const int* __restrict__ src, const int* __restrict__ dst) {
    int i = blockIdx.x * blockDim.x + threadIdx.x;
    if (i < NN) {
        int b = min(g_deg[i], MAXD);
        g_norder[g_border[b] + atomicAdd(&g_bcur[b], 1)] = i;
    }
    if (i < EE) {
        int d = dst[i];
        int pos = atomicAdd(&g_cursor[d], 1);
        g_csr[g_rowptr[d] + pos] = src[i];
    }
}

// ---------------- pack W: [b][n][k] k-major, bf16 hi/lo ----------------
__global__ void k_pack_w(const float* __restrict__ Wl, const float* __restrict__ Wr) {
    __shared__ float tile[32][33];
    int b = blockIdx.z >> 1, half = blockIdx.z & 1;
    int k0 = blockIdx.x * 32, n0 = blockIdx.y * 32;
    const float* W = (half ? Wr : Wl) + (size_t)b * 512 * 512;
    int tx = threadIdx.x, ty = threadIdx.y;      // (32, 8)
#pragma unroll
    for (int dy = 0; dy < 32; dy += 8)
        tile[ty + dy][tx] = W[(size_t)(k0 + ty + dy) * 512 + n0 + tx];
    __syncthreads();
#pragma unroll
    for (int dy = 0; dy < 32; dy += 8) {
        int n = n0 + ty + dy;
        float v = tile[tx][ty + dy];
        __nv_bfloat16 h = __float2bfloat16(v);
        __nv_bfloat16 l = __float2bfloat16(v - __bfloat162float(h));
        size_t o = ((size_t)b * 512 + n) * 1024 + (size_t)half * 512 + k0 + tx;
        g_Whi[o] = h;
        g_Wlo[o] = l;
    }
}

// ---------------- fused neighbor-sum + bf16 pack (per permuted row) ----------------
__global__ void k_aggh_pack(const float* __restrict__ feats) {
    int row = blockIdx.x;
    if (row >= g_border[11]) return;
    int t = threadIdx.x;                  // 128 threads, 4 float cols each
    int node = g_norder[row];
    float hv[4] = {0.f, 0.f, 0.f, 0.f};
    float fv[4] = {0.f, 0.f, 0.f, 0.f};
    if (node >= 0) {
        const float4* f4 = reinterpret_cast<const float4*>(feats);
        int beg = g_rowptr[node], end = g_rowptr[node + 1];
        for (int j = beg; j < end; j++) {
            float4 v = f4[(size_t)g_csr[j] * 128 + t];
            hv[0] += v.x; hv[1] += v.y; hv[2] += v.z; hv[3] += v.w;
        }
        float4 f = f4[(size_t)node * 128 + t];
        fv[0] = f.x; fv[1] = f.y; fv[2] = f.z; fv[3] = f.w;
    }
    ushort4 hh, hl, fh, fl;
    unsigned short* ph = &hh.x; unsigned short* pl = &hl.x;
    unsigned short* qh = &fh.x; unsigned short* ql = &fl.x;
#pragma unroll
    for (int j = 0; j < 4; j++) {
        __nv_bfloat16 a = __float2bfloat16(hv[j]);
        __nv_bfloat16 b = __float2bfloat16(hv[j] - __bfloat162float(a));
        ph[j] = __bfloat16_as_ushort(a); pl[j] = __bfloat16_as_ushort(b);
        __nv_bfloat16 c = __float2bfloat16(fv[j]);
        __nv_bfloat16 d = __float2bfloat16(fv[j] - __bfloat162float(c));
        qh[j] = __bfloat16_as_ushort(c); ql[j] = __bfloat16_as_ushort(d);
    }
    size_t base = (size_t)row * 1024 + t * 4;
    *reinterpret_cast<ushort4*>(&g_Ah[base])       = hh;
    *reinterpret_cast<ushort4*>(&g_Al[base])       = hl;
    *reinterpret_cast<ushort4*>(&g_Ah[base + 512]) = fh;
    *reinterpret_cast<ushort4*>(&g_Al[base + 512]) = fl;
}

// ---------------- warp-MMA grouped GEMM ----------------
// CTA 128m x 256n, 512 threads (16 warps, warp 32m x 64n), K-chunk 32, 96 chunks
#define KCH 32
#define NCHUNK 96
#define A_BYTES (128 * 64)            // 8192
#define B_BYTES (256 * 64)            // 16384
#define STAGE (A_BYTES + B_BYTES)     // 24576; 2 stages = 49152 (static max)

__device__ __forceinline__ void issue_chunk(uint32_t sbase, int c, int row0,
                                            int colbase, int b, int tid) {
    int pass = c >> 5, kc = (c & 31) * KCH;
    const __nv_bfloat16* Asrc = (pass < 2) ? g_Ah : g_Al;
    const __nv_bfloat16* Bsrc = (pass == 1) ? g_Wlo : g_Whi;
    {   // A: 128 rows x 4 segs = 512, one per thread
        int row = tid >> 2, seg = tid & 3;
        cp_async16(sbase + swz(row, seg),
                   Asrc + (size_t)(row0 + row) * 1024 + kc + seg * 8);
    }
#pragma unroll
    for (int u = tid; u < 1024; u += 512) {  // B: 256 rows x 4 segs
        int row = u >> 2, seg = u & 3;
        cp_async16(sbase + A_BYTES + swz(row, seg),
                   Bsrc + ((size_t)b * 512 + colbase + row) * 1024 + kc + seg * 8);
    }
}

__global__ void __launch_bounds__(512, 1)
k_gemm_hmma(const float* __restrict__ bl) {
    int row0 = blockIdx.y * 128;
    if (row0 >= g_border[11]) return;
    int colbase = blockIdx.x * 256;
    int b = 0;
    while (b < 10 && row0 >= g_border[b + 1]) b++;

    __shared__ __align__(128) char sbuf[2][STAGE];

    int tid = threadIdx.x, w = tid >> 5, lane = tid & 31;
    uint32_t s0 = smem_u32(sbuf[0]);
    uint32_t s1 = smem_u32(sbuf[1]);

    float c[2][8][4];
#pragma unroll
    for (int i = 0; i < 2; i++)
#pragma unroll
        for (int j = 0; j < 8; j++)
#pragma unroll
            for (int q = 0; q < 4; q++) c[i][j][q] = 0.f;

    int mw = (w & 3) * 32, nw = (w >> 2) * 64;

    issue_chunk(s0, 0, row0, colbase, b, tid);
    CP_COMMIT();

#pragma unroll 1
    for (int i = 0; i < NCHUNK; i++) {
        if (i + 1 < NCHUNK)
            issue_chunk((i + 1) & 1 ? s1 : s0, i + 1, row0, colbase, b, tid);
        CP_COMMIT();
        CP_WAIT1();
        __syncthreads();

        uint32_t sa = (i & 1) ? s1 : s0;
        uint32_t sb = sa + A_BYTES;
#pragma unroll
        for (int ks = 0; ks < 2; ks++) {
            uint32_t a[2][4];
#pragma unroll
            for (int am = 0; am < 2; am++) {
                int row = mw + am * 16 + (lane & 15);
                int seg = ks * 2 + (lane >> 4);
                ldsm4(a[am], sa + swz(row, seg));
            }
            uint32_t bf[4][4];
#pragma unroll
            for (int bp = 0; bp < 4; bp++) {
                int row = nw + bp * 16 + (lane & 7) + (lane >> 4) * 8;
                int seg = ks * 2 + ((lane >> 3) & 1);
                ldsm4(bf[bp], sb + swz(row, seg));
            }
#pragma unroll
            for (int am = 0; am < 2; am++)
#pragma unroll
                for (int bp = 0; bp < 4; bp++) {
                    mma16816(c[am][bp * 2 + 0], a[am], &bf[bp][0]);
                    mma16816(c[am][bp * 2 + 1], a[am], &bf[bp][2]);
                }
        }
        __syncthreads();
    }

    // epilogue: + bias, scatter rows to g_pre[node] (nodes read from global)
#pragma unroll
    for (int am = 0; am < 2; am++) {
        int mloc = mw + am * 16 + (lane >> 2);
#pragma unroll
        for (int half = 0; half < 2; half++) {
            int node = g_norder[row0 + mloc + half * 8];
            if (node < 0) continue;
#pragma unroll
            for (int bn = 0; bn < 8; bn++) {
                int col = colbase + nw + bn * 8 + (lane & 3) * 2;
                float bb0 = bl[(size_t)b * 512 + col];
                float bb1 = bl[(size_t)b * 512 + col + 1];
                float2 v = make_float2(c[am][bn][half * 2 + 0] + bb0,
                                       c[am][bn][half * 2 + 1] + bb1);
                *reinterpret_cast<float2*>(&g_pre[(size_t)node * 512 + col]) = v;
            }
        }
    }
}

// ---------------- BN stats ----------------
__global__ void k_bnstats() {
    int r0 = blockIdx.x * 128;
    int r1 = min(r0 + 128, NN);
    int t = threadIdx.x;
    float s0 = 0.f, q0 = 0.f, s1 = 0.f, q1 = 0.f;
    for (int r = r0; r < r1; r++) {
        float v0 = g_pre[(size_t)r * DD + t];
        float v1 = g_pre[(size_t)r * DD + t + 256];
        s0 += v0; q0 += v0 * v0;
        s1 += v1; q1 += v1 * v1;
    }
    atomicAdd(&g_sum[t], s0);       atomicAdd(&g_sumsq[t], q0);
    atomicAdd(&g_sum[t + 256], s1); atomicAdd(&g_sumsq[t + 256], q1);
}

// ---------------- max aggregation, BN finalized inline ----------------
__global__ void k_maxagg(const float* __restrict__ gamma, const float* __restrict__ beta,
                         float* __restrict__ out) {
    int n = blockIdx.x;
    int t = threadIdx.x;                       // 128 threads, float4 lanes
    float4 sum = reinterpret_cast<const float4*>(g_sum)[t];
    float4 sq  = reinterpret_cast<const float4*>(g_sumsq)[t];
    float4 gm  = reinterpret_cast<const float4*>(gamma)[t];
    float4 bt  = reinterpret_cast<const float4*>(beta)[t];
    const float inv = 1.f / (float)NN;
    float4 sc, sh;
    {
        float m;
        m = sum.x * inv; sc.x = gm.x * rsqrtf(sq.x * inv - m * m + BN_EPS); sh.x = bt.x - m * sc.x;
        m = sum.y * inv; sc.y = gm.y * rsqrtf(sq.y * inv - m * m + BN_EPS); sh.y = bt.y - m * sc.y;
        m = sum.z * inv; sc.z = gm.z * rsqrtf(sq.z * inv - m * m + BN_EPS); sh.z = bt.z - m * sc.z;
        m = sum.w * inv; sc.w = gm.w * rsqrtf(sq.w * inv - m * m + BN_EPS); sh.w = bt.w - m * sc.w;
    }
    const float4* p4 = reinterpret_cast<const float4*>(g_pre);
    float4 v = p4[(size_t)n * 128 + t];
    float4 m4 = make_float4(v.x * sc.x + sh.x, v.y * sc.y + sh.y,
                            v.z * sc.z + sh.z, v.w * sc.w + sh.w);
    int beg = g_rowptr[n], end = g_rowptr[n + 1];
    for (int j = beg; j < end; j++) {
        float4 wv = p4[(size_t)g_csr[j] * 128 + t];
        m4.x = fmaxf(m4.x, wv.x * sc.x + sh.x);
        m4.y = fmaxf(m4.y, wv.y * sc.y + sh.y);
        m4.z = fmaxf(m4.z, wv.z * sc.z + sh.z);
        m4.w = fmaxf(m4.w, wv.w * sc.w + sh.w);
    }
    reinterpret_cast<float4*>(out)[(size_t)n * 128 + t] = m4;
}

// ---------------- launch ----------------
extern "C" void kernel_launch(void* const* d_in, const int* in_sizes, int n_in,
                              void* d_out, int out_size) {
    const float* feats = (const float*)d_in[0];
    const int*   src   = (const int*)  d_in[1];
    const int*   dst   = (const int*)  d_in[2];
    const float* Wl    = (const float*)d_in[3];
    const float* Wr    = (const float*)d_in[4];
    const float* bl    = (const float*)d_in[5];
    const float* gamma = (const float*)d_in[6];
    const float* beta  = (const float*)d_in[7];
    float* out = (float*)d_out;

    k_zero<<<(NORD + 255) / 256, 256>>>();
    k_hist<<<(EE + 255) / 256, 256>>>(dst);
    k_scan<<<1, 1024>>>();
    k_scatter_fill<<<(EE + 255) / 256, 256>>>(src, dst);
    k_pack_w<<<dim3(16, 16, 22), dim3(32, 8)>>>(Wl, Wr);
    k_aggh_pack<<<NORD, 128>>>(feats);
    k_gemm_hmma<<<dim3(2, 168), 512>>>(bl);
    k_bnstats<<<(NN + 127) / 128, 256>>>();
    k_maxagg<<<NN, 128>>>(gamma, beta, out);
}

// round 14
// speedup vs baseline: 2.1472x; 1.1667x over previous
#include <cuda_runtime.h>
#include <cuda_bf16.h>
#include <cstdint>

#define NN   20000
#define EE   160000
#define DD   512
#define MAXD 10
#define BN_EPS 1e-5f

#define PAD 128
#define NORD (NN + 11*PAD)           // 21408

// ---------------- device scratch ----------------
__device__ float g_pre[NN * DD];
__device__ int   g_deg[NN];
__device__ int   g_rowptr[NN + 1];
__device__ int   g_cursor[NN];
__device__ int   g_csr[EE];
__device__ int   g_bcur[11];
__device__ int   g_border[12];
__device__ int   g_norder[NORD];
__device__ float g_sum[DD];
__device__ float g_sumsq[DD];
// packed bf16 operands (hi/lo split), rows permuted by bucket: [row][h(512)|feats(512)]
__device__ __nv_bfloat16 g_Ah[(size_t)NORD * 1024];
__device__ __nv_bfloat16 g_Al[(size_t)NORD * 1024];
__device__ __nv_bfloat16 g_Whi[(size_t)11 * 512 * 1024];   // [b][n][k] k-major
__device__ __nv_bfloat16 g_Wlo[(size_t)11 * 512 * 1024];

// ---------------- PTX helpers (compute_103-safe) ----------------
__device__ __forceinline__ uint32_t smem_u32(const void* p) {
    uint32_t a;
    asm("{ .reg .u64 t; cvta.to.shared.u64 t, %1; cvt.u32.u64 %0, t; }" : "=r"(a) : "l"(p));
    return a;
}
__device__ __forceinline__ void cp_async16(uint32_t sdst, const void* gsrc) {
    asm volatile("cp.async.cg.shared.global [%0], [%1], 16;" :: "r"(sdst), "l"(gsrc));
}
#define CP_COMMIT() asm volatile("cp.async.commit_group;" ::: "memory")
#define CP_WAIT1()  asm volatile("cp.async.wait_group 1;" ::: "memory")
#define CP_WAIT0()  asm volatile("cp.async.wait_group 0;" ::: "memory")

__device__ __forceinline__ void ldsm4(uint32_t* r, uint32_t addr) {
    asm volatile("ldmatrix.sync.aligned.m8n8.x4.shared.b16 {%0,%1,%2,%3}, [%4];"
                 : "=r"(r[0]), "=r"(r[1]), "=r"(r[2]), "=r"(r[3]) : "r"(addr));
}
__device__ __forceinline__ void mma16816(float* c, const uint32_t* a, const uint32_t* b) {
    asm volatile(
        "mma.sync.aligned.m16n8k16.row.col.f32.bf16.bf16.f32 "
        "{%0,%1,%2,%3}, {%4,%5,%6,%7}, {%8,%9}, {%0,%1,%2,%3};"
        : "+f"(c[0]), "+f"(c[1]), "+f"(c[2]), "+f"(c[3])
        : "r"(a[0]), "r"(a[1]), "r"(a[2]), "r"(a[3]), "r"(b[0]), "r"(b[1]));
}

// canonical SW128 swizzle for 128B-pitch rows
__device__ __forceinline__ uint32_t swz128(uint32_t off) {
    return off ^ ((off >> 3) & 0x70);
}

// ---------------- pack W (+ global zero-init, launch #0) ----------------
__global__ void k_pack_w(const float* __restrict__ Wl, const float* __restrict__ Wr) {
    // fold scratch zeroing into this first launch
    {
        int bid = blockIdx.x + gridDim.x * (blockIdx.y + gridDim.y * blockIdx.z);
        int g = bid * 256 + threadIdx.y * 32 + threadIdx.x;
        if (g < NN)   { g_deg[g] = 0; g_cursor[g] = 0; }
        if (g < NORD) { g_norder[g] = -1; }
        if (g < DD)   { g_sum[g] = 0.f; g_sumsq[g] = 0.f; }
        if (g < 11)   { g_bcur[g] = 0; }
    }
    __shared__ float tile[32][33];
    int b = blockIdx.z >> 1, half = blockIdx.z & 1;
    int k0 = blockIdx.x * 32, n0 = blockIdx.y * 32;
    const float* W = (half ? Wr : Wl) + (size_t)b * 512 * 512;
    int tx = threadIdx.x, ty = threadIdx.y;      // (32, 8)
#pragma unroll
    for (int dy = 0; dy < 32; dy += 8)
        tile[ty + dy][tx] = W[(size_t)(k0 + ty + dy) * 512 + n0 + tx];
    __syncthreads();
#pragma unroll
    for (int dy = 0; dy < 32; dy += 8) {
        int n = n0 + ty + dy;
        float v = tile[tx][ty + dy];
        __nv_bfloat16 h = __float2bfloat16(v);
        __nv_bfloat16 l = __float2bfloat16(v - __bfloat162float(h));
        size_t o = ((size_t)b * 512 + n) * 1024 + (size_t)half * 512 + k0 + tx;
        g_Whi[o] = h;
        g_Wlo[o] = l;
    }
}

__global__ void k_hist(const int* __restrict__ dst) {
    int e = blockIdx.x * blockDim.x + threadIdx.x;
    if (e < EE) atomicAdd(&g_deg[dst[e]], 1);
}

// single block: exclusive scan of deg -> rowptr, bucket counts -> padded borders
__global__ void k_scan() {
    __shared__ int warp_sums[32];
    __shared__ int s_bcnt[11];
    __shared__ int s_carry;
    int t = threadIdx.x, lane = t & 31, w = t >> 5;
    if (t < 11) s_bcnt[t] = 0;
    if (t == 0) s_carry = 0;
    __syncthreads();
    for (int base = 0; base < NN; base += 1024) {
        int i = base + t;
        int v = (i < NN) ? g_deg[i] : 0;
        if (i < NN) atomicAdd(&s_bcnt[min(v, MAXD)], 1);
        int x = v;
#pragma unroll
        for (int o = 1; o < 32; o <<= 1) {
            int y = __shfl_up_sync(~0u, x, o);
            if (lane >= o) x += y;
        }
        if (lane == 31) warp_sums[w] = x;
        __syncthreads();
        if (w == 0) {
            int s = warp_sums[lane];
#pragma unroll
            for (int o = 1; o < 32; o <<= 1) {
                int y = __shfl_up_sync(~0u, s, o);
                if (lane >= o) s += y;
            }
            warp_sums[lane] = s;
        }
        __syncthreads();
        int prefix = s_carry + (w ? warp_sums[w - 1] : 0);
        if (i < NN) g_rowptr[i] = prefix + x - v;
        __syncthreads();
        if (t == 0) s_carry += warp_sums[31];
        __syncthreads();
    }
    if (t == 0) {
        g_rowptr[NN] = s_carry;
        int off = 0;
        for (int b = 0; b < 11; b++) {
            g_border[b] = off;
            off += (s_bcnt[b] + PAD - 1) & ~(PAD - 1);
        }
        g_border[11] = off;
    }
}

__global__ void k_scatter_fill(const int* __restrict__ src, const int* __restrict__ dst) {
    int i = blockIdx.x * blockDim.x + threadIdx.x;
    if (i < NN) {
        int b = min(g_deg[i], MAXD);
        g_norder[g_border[b] + atomicAdd(&g_bcur[b], 1)] = i;
    }
    if (i < EE) {
        int d = dst[i];
        int pos = atomicAdd(&g_cursor[d], 1);
        g_csr[g_rowptr[d] + pos] = src[i];
    }
}

// ---------------- fused neighbor-sum + bf16 pack (per permuted row) ----------------
__global__ void k_aggh_pack(const float* __restrict__ feats) {
    int row = blockIdx.x;
    if (row >= g_border[11]) return;
    int t = threadIdx.x;                  // 128 threads, 4 float cols each
    int node = g_norder[row];
    float hv[4] = {0.f, 0.f, 0.f, 0.f};
    float fv[4] = {0.f, 0.f, 0.f, 0.f};
    if (node >= 0) {
        const float4* f4 = reinterpret_cast<const float4*>(feats);
        int beg = g_rowptr[node], end = g_rowptr[node + 1];
        for (int j = beg; j < end; j++) {
            float4 v = f4[(size_t)g_csr[j] * 128 + t];
            hv[0] += v.x; hv[1] += v.y; hv[2] += v.z; hv[3] += v.w;
        }
        float4 f = f4[(size_t)node * 128 + t];
        fv[0] = f.x; fv[1] = f.y; fv[2] = f.z; fv[3] = f.w;
    }
    ushort4 hh, hl, fh, fl;
    unsigned short* ph = &hh.x; unsigned short* pl = &hl.x;
    unsigned short* qh = &fh.x; unsigned short* ql = &fl.x;
#pragma unroll
    for (int j = 0; j < 4; j++) {
        __nv_bfloat16 a = __float2bfloat16(hv[j]);
        __nv_bfloat16 b = __float2bfloat16(hv[j] - __bfloat162float(a));
        ph[j] = __bfloat16_as_ushort(a); pl[j] = __bfloat16_as_ushort(b);
        __nv_bfloat16 c = __float2bfloat16(fv[j]);
        __nv_bfloat16 d = __float2bfloat16(fv[j] - __bfloat162float(c));
        qh[j] = __bfloat16_as_ushort(c); ql[j] = __bfloat16_as_ushort(d);
    }
    size_t base = (size_t)row * 1024 + t * 4;
    *reinterpret_cast<ushort4*>(&g_Ah[base])       = hh;
    *reinterpret_cast<ushort4*>(&g_Al[base])       = hl;
    *reinterpret_cast<ushort4*>(&g_Ah[base + 512]) = fh;
    *reinterpret_cast<ushort4*>(&g_Al[base + 512]) = fl;
}

// ---------------- warp-MMA grouped GEMM ----------------
// CTA 128m x 256n, 512 threads (16 warps, warp 32m x 64n)
// K-chunk 64, 48 chunks (3 bf16 passes x 1024K), 3-stage cp.async ring, 1 sync/chunk
#define KCH 64
#define NCHUNK 48
#define A_BYTES (128 * 128)            // 16384
#define B_BYTES (256 * 128)            // 32768
#define STAGE (A_BYTES + B_BYTES)      // 49152
#define NSTAGE 3
#define DYN_SMEM (NSTAGE * STAGE)      // 147456

__device__ __forceinline__ void issue_chunk(uint32_t sbase, int c, int row0,
                                            int colbase, int b, int tid) {
    int pass = c >> 4, kc = (c & 15) * KCH;
    const __nv_bfloat16* Asrc = (pass < 2) ? g_Ah : g_Al;
    const __nv_bfloat16* Bsrc = (pass == 1) ? g_Wlo : g_Whi;
#pragma unroll
    for (int u = tid; u < 1024; u += 512) {        // A: 128 rows x 8 segs
        int row = u >> 3, seg = u & 7;
        cp_async16(sbase + swz128(row * 128 + seg * 16),
                   Asrc + (size_t)(row0 + row) * 1024 + kc + seg * 8);
    }
#pragma unroll
    for (int u = tid; u < 2048; u += 512) {        // B: 256 rows x 8 segs
        int row = u >> 3, seg = u & 7;
        cp_async16(sbase + A_BYTES + swz128(row * 128 + seg * 16),
                   Bsrc + ((size_t)b * 512 + colbase + row) * 1024 + kc + seg * 8);
    }
}

__global__ void __launch_bounds__(512, 1)
k_gemm_hmma(const float* __restrict__ bl) {
    int row0 = blockIdx.y * 128;
    if (row0 >= g_border[11]) return;
    int colbase = blockIdx.x * 256;
    int b = 0;
    while (b < 10 && row0 >= g_border[b + 1]) b++;

    extern __shared__ __align__(128) char sbuf[];
    uint32_t sb0 = smem_u32(sbuf);

    int tid = threadIdx.x, w = tid >> 5, lane = tid & 31;

    float c[2][8][4];
#pragma unroll
    for (int i = 0; i < 2; i++)
#pragma unroll
        for (int j = 0; j < 8; j++)
#pragma unroll
            for (int q = 0; q < 4; q++) c[i][j][q] = 0.f;

    int mw = (w & 3) * 32, nw = (w >> 2) * 64;

    issue_chunk(sb0, 0, row0, colbase, b, tid);
    CP_COMMIT();
    issue_chunk(sb0 + STAGE, 1, row0, colbase, b, tid);
    CP_COMMIT();

#pragma unroll 1
    for (int i = 0; i < NCHUNK; i++) {
        if (i == NCHUNK - 1) CP_WAIT0(); else CP_WAIT1();
        __syncthreads();
        if (i + 2 < NCHUNK) {
            issue_chunk(sb0 + ((i + 2) % NSTAGE) * STAGE, i + 2, row0, colbase, b, tid);
            CP_COMMIT();
        }
        uint32_t sa = sb0 + (i % NSTAGE) * STAGE;
        uint32_t sbB = sa + A_BYTES;
#pragma unroll
        for (int ks = 0; ks < 4; ks++) {
            uint32_t a[2][4];
#pragma unroll
            for (int am = 0; am < 2; am++) {
                int row = mw + am * 16 + (lane & 15);
                uint32_t col = ks * 32 + (lane >> 4) * 16;
                ldsm4(a[am], sa + swz128(row * 128 + col));
            }
            uint32_t bf[4][4];
#pragma unroll
            for (int bp = 0; bp < 4; bp++) {
                int row = nw + bp * 16 + (lane & 7) + (lane >> 4) * 8;
                uint32_t col = ks * 32 + ((lane >> 3) & 1) * 16;
                ldsm4(bf[bp], sbB + swz128(row * 128 + col));
            }
#pragma unroll
            for (int am = 0; am < 2; am++)
#pragma unroll
                for (int bp = 0; bp < 4; bp++) {
                    mma16816(c[am][bp * 2 + 0], a[am], &bf[bp][0]);
                    mma16816(c[am][bp * 2 + 1], a[am], &bf[bp][2]);
                }
        }
    }

    // epilogue: + bias, scatter rows to g_pre[node]
#pragma unroll
    for (int am = 0; am < 2; am++) {
        int mloc = mw + am * 16 + (lane >> 2);
#pragma unroll
        for (int half = 0; half < 2; half++) {
            int node = g_norder[row0 + mloc + half * 8];
            if (node < 0) continue;
#pragma unroll
            for (int bn = 0; bn < 8; bn++) {
                int col = colbase + nw + bn * 8 + (lane & 3) * 2;
                float bb0 = bl[(size_t)b * 512 + col];
                float bb1 = bl[(size_t)b * 512 + col + 1];
                float2 v = make_float2(c[am][bn][half * 2 + 0] + bb0,
                                       c[am][bn][half * 2 + 1] + bb1);
                *reinterpret_cast<float2*>(&g_pre[(size_t)node * 512 + col]) = v;
            }
        }
    }
}

// ---------------- BN stats ----------------
__global__ void k_bnstats() {
    int r0 = blockIdx.x * 128;
    int r1 = min(r0 + 128, NN);
    int t = threadIdx.x;
    float s0 = 0.f, q0 = 0.f, s1 = 0.f, q1 = 0.f;
    for (int r = r0; r < r1; r++) {
        float v0 = g_pre[(size_t)r * DD + t];
        float v1 = g_pre[(size_t)r * DD + t + 256];
        s0 += v0; q0 += v0 * v0;
        s1 += v1; q1 += v1 * v1;
    }
    atomicAdd(&g_sum[t], s0);       atomicAdd(&g_sumsq[t], q0);
    atomicAdd(&g_sum[t + 256], s1); atomicAdd(&g_sumsq[t + 256], q1);
}

// ---------------- max aggregation, BN finalized inline ----------------
__global__ void k_maxagg(const float* __restrict__ gamma, const float* __restrict__ beta,
                         float* __restrict__ out) {
    int n = blockIdx.x;
    int t = threadIdx.x;
    float4 sum = reinterpret_cast<const float4*>(g_sum)[t];
    float4 sq  = reinterpret_cast<const float4*>(g_sumsq)[t];
    float4 gm  = reinterpret_cast<const float4*>(gamma)[t];
    float4 bt  = reinterpret_cast<const float4*>(beta)[t];
    const float inv = 1.f / (float)NN;
    float4 sc, sh;
    {
        float m;
        m = sum.x * inv; sc.x = gm.x * rsqrtf(sq.x * inv - m * m + BN_EPS); sh.x = bt.x - m * sc.x;
        m = sum.y * inv; sc.y = gm.y * rsqrtf(sq.y * inv - m * m + BN_EPS); sh.y = bt.y - m * sc.y;
        m = sum.z * inv; sc.z = gm.z * rsqrtf(sq.z * inv - m * m + BN_EPS); sh.z = bt.z - m * sc.z;
        m = sum.w * inv; sc.w = gm.w * rsqrtf(sq.w * inv - m * m + BN_EPS); sh.w = bt.w - m * sc.w;
    }
    const float4* p4 = reinterpret_cast<const float4*>(g_pre);
    float4 v = p4[(size_t)n * 128 + t];
    float4 m4 = make_float4(v.x * sc.x + sh.x, v.y * sc.y + sh.y,
                            v.z * sc.z + sh.z, v.w * sc.w + sh.w);
    int beg = g_rowptr[n], end = g_rowptr[n + 1];
    for (int j = beg; j < end; j++) {
        float4 wv = p4[(size_t)g_csr[j] * 128 + t];
        m4.x = fmaxf(m4.x, wv.x * sc.x + sh.x);
        m4.y = fmaxf(m4.y, wv.y * sc.y + sh.y);
        m4.z = fmaxf(m4.z, wv.z * sc.z + sh.z);
        m4.w = fmaxf(m4.w, wv.w * sc.w + sh.w);
    }
    reinterpret_cast<float4*>(out)[(size_t)n * 128 + t] = m4;
}

// ---------------- launch ----------------
extern "C" void kernel_launch(void* const* d_in, const int* in_sizes, int n_in,
                              void* d_out, int out_size) {
    const float* feats = (const float*)d_in[0];
    const int*   src   = (const int*)  d_in[1];
    const int*   dst   = (const int*)  d_in[2];
    const float* Wl    = (const float*)d_in[3];
    const float* Wr    = (const float*)d_in[4];
    const float* bl    = (const float*)d_in[5];
    const float* gamma = (const float*)d_in[6];
    const float* beta  = (const float*)d_in[7];
    float* out = (float*)d_out;

    // idempotent; ignore return (already set after first call)
    cudaFuncSetAttribute(k_gemm_hmma, cudaFuncAttributeMaxDynamicSharedMemorySize, DYN_SMEM);

    k_pack_w<<<dim3(16, 16, 22), dim3(32, 8)>>>(Wl, Wr);          // 0 (+ scratch zero)
    k_hist<<<(EE + 255) / 256, 256>>>(dst);                        // 1
    k_scan<<<1, 1024>>>();                                         // 2
    k_scatter_fill<<<(EE + 255) / 256, 256>>>(src, dst);           // 3
    k_aggh_pack<<<NORD, 128>>>(feats);                             // 4
    k_gemm_hmma<<<dim3(2, 168), 512, DYN_SMEM>>>(bl);              // 5  <- ncu -s 5
    k_bnstats<<<(NN + 127) / 128, 256>>>();                        // 6
    k_maxagg<<<NN, 128>>>(gamma, beta, out);                       // 7
}